// round 12
// baseline (speedup 1.0000x reference)
#include <cuda_runtime.h>
#include <cuda_fp16.h>
#include <math.h>
#include <cstdint>

#define S_LEN 4096
#define DIM   256
#define MROWS 8192
#define IN_F  768
#define KEXP  6912
#define PIECE (3ull * MROWS * DIM)
#define NROWS (3 * MROWS)
#define QS2   0.3002806f    // sqrt(log2(e)/16), applied to both Q and K

__device__ __half g_Ah[(size_t)MROWS * KEXP];
__device__ __half g_Wh[(size_t)DIM * KEXP];
__device__ __half g_T16[3ull * MROWS * DIM];
__device__ __half g_Wqkv[768ull * DIM];
__device__ float  g_bqkv[768];
__device__ uint8_t g_Q8[3ull * MROWS * DIM];
__device__ uint8_t g_K8[3ull * MROWS * DIM];
__device__ __half  g_Vb[3ull * MROWS * DIM];
__device__ float g_Ap[3ull * PIECE];
__device__ float g_L[3 * NROWS];
__device__ float g_Kp[2ull * MROWS * DIM];

// ======================= PTX helpers (baseline sm_103) =====================
__device__ __forceinline__ uint32_t smem_u32(const void* p) {
    uint32_t a;
    asm("{ .reg .u64 t; cvta.to.shared.u64 t, %1; cvt.u32.u64 %0, t; }" : "=r"(a) : "l"(p));
    return a;
}
#define LDSM4(d0, d1, d2, d3, a)                                                        \
    asm volatile("ldmatrix.sync.aligned.m8n8.x4.shared.b16 {%0,%1,%2,%3}, [%4];"        \
                 : "=r"(d0), "=r"(d1), "=r"(d2), "=r"(d3) : "r"(a))
#define LDSM4T(d0, d1, d2, d3, a)                                                       \
    asm volatile("ldmatrix.sync.aligned.m8n8.x4.trans.shared.b16 {%0,%1,%2,%3}, [%4];"  \
                 : "=r"(d0), "=r"(d1), "=r"(d2), "=r"(d3) : "r"(a))
#define MMAH(c, a0, a1, a2, a3, b0, b1)                                                 \
    asm volatile("mma.sync.aligned.m16n8k16.row.col.f32.f16.f16.f32 "                   \
                 "{%0,%1,%2,%3}, {%4,%5,%6,%7}, {%8,%9}, {%0,%1,%2,%3};"                \
                 : "+f"((c)[0]), "+f"((c)[1]), "+f"((c)[2]), "+f"((c)[3])               \
                 : "r"(a0), "r"(a1), "r"(a2), "r"(a3), "r"(b0), "r"(b1))
#define MMAF8(c, a0, a1, a2, a3, b0, b1)                                                \
    asm volatile("mma.sync.aligned.m16n8k32.row.col.f32.e4m3.e4m3.f32 "                 \
                 "{%0,%1,%2,%3}, {%4,%5,%6,%7}, {%8,%9}, {%0,%1,%2,%3};"                \
                 : "+f"((c)[0]), "+f"((c)[1]), "+f"((c)[2]), "+f"((c)[3])               \
                 : "r"(a0), "r"(a1), "r"(a2), "r"(a3), "r"(b0), "r"(b1))
#define CPA16(d, s) asm volatile("cp.async.cg.shared.global [%0], [%1], 16;" :: "r"(d), "l"(s))
#define CPCOMMIT()  asm volatile("cp.async.commit_group;" ::: "memory")
#define CPWAIT2()   asm volatile("cp.async.wait_group 2;" ::: "memory")
#define CPWAIT1()   asm volatile("cp.async.wait_group 1;" ::: "memory")
#define CPWAIT0()   asm volatile("cp.async.wait_group 0;" ::: "memory")
#define EX2H2(d, s) asm("ex2.approx.f16x2 %0, %1;" : "=r"(d) : "r"(s))
#define CVTE4(d, lo, hi) \
    asm("cvt.rn.satfinite.e4m3x2.f32 %0, %1, %2;" : "=h"(d) : "f"(hi), "f"(lo))

// ================== HMMA GEMM: C[M,N] = A[M,K] @ W[N,K]^T ==================
// MODE 0: KAN split-K (z = K-piece, fp32 partial out).
// MODE 1: QKV (z = view; Q,K -> e4m3 scaled by QS2; V -> fp16).
template <int MODE>
__global__ void __launch_bounds__(256) hgemm(const __half* __restrict__ A,
                                             const __half* __restrict__ W,
                                             const float* __restrict__ bias,
                                             void* __restrict__ C0,
                                             void* __restrict__ C1,
                                             void* __restrict__ C2,
                                             int M, int N, int Kst, int Klen) {
    __shared__ __align__(16) char sA[3][8192];
    __shared__ __align__(16) char sW[3][8192];
    uint32_t aB = smem_u32(sA), wB = smem_u32(sW);
    int tid = threadIdx.x, lane = tid & 31, w = tid >> 5;
    int wm = w >> 2, wn = w & 3;
    int m0 = blockIdx.y << 7, n0 = blockIdx.x << 7;
    int z = blockIdx.z;
    int lrow = lane & 7, lhalf = (lane >> 3) & 1, lhi = lane >> 4;

    const __half* Ab = (MODE == 0) ? A + (size_t)z * Klen : A + (size_t)z * MROWS * DIM;
    const __half* Wb = (MODE == 0) ? W + (size_t)z * Klen : W;

    int r0 = tid >> 2, c0 = tid & 3;
    int r1 = (tid + 256) >> 2, c1 = (tid + 256) & 3;
    uint32_t dA0 = r0 * 64 + ((c0 ^ ((r0 >> 1) & 3)) << 4);
    uint32_t dA1 = r1 * 64 + ((c1 ^ ((r1 >> 1) & 3)) << 4);
    const __half* As0 = Ab + (size_t)(m0 + r0) * Kst + c0 * 8;
    const __half* As1 = Ab + (size_t)(m0 + r1) * Kst + c1 * 8;
    const __half* Ws0 = Wb + (size_t)(n0 + r0) * Kst + c0 * 8;
    const __half* Ws1 = Wb + (size_t)(n0 + r1) * Kst + c1 * 8;

    int rowA[4], xrA[4];
#pragma unroll
    for (int mi = 0; mi < 4; mi++) {
        rowA[mi] = wm * 64 + mi * 16 + lrow + (lhalf << 3);
        xrA[mi] = (rowA[mi] >> 1) & 3;
    }
    int rowW[2], xrW[2];
#pragma unroll
    for (int ng = 0; ng < 2; ng++) {
        rowW[ng] = wn * 32 + ng * 16 + lrow + (lhalf << 3);
        xrW[ng] = (rowW[ng] >> 1) & 3;
    }

    float oacc[4][4][4];
#pragma unroll
    for (int i = 0; i < 4; i++)
#pragma unroll
        for (int j = 0; j < 4; j++)
#pragma unroll
            for (int e = 0; e < 4; e++) oacc[i][j][e] = 0.0f;

    int KT = Klen >> 5;
    auto issue = [&](int kt) {
        uint32_t so = (uint32_t)(kt % 3) * 8192;
        int nk = kt << 5;
        CPA16(aB + so + dA0, As0 + nk); CPA16(aB + so + dA1, As1 + nk);
        CPA16(wB + so + dA0, Ws0 + nk); CPA16(wB + so + dA1, Ws1 + nk);
        CPCOMMIT();
    };
    issue(0);
    issue(1);

    for (int kt = 0; kt < KT; kt++) {
        if (kt + 2 < KT) { issue(kt + 2); CPWAIT2(); }
        else if (kt + 1 < KT) { CPWAIT1(); }
        else { CPWAIT0(); }
        __syncthreads();
        uint32_t so = (uint32_t)(kt % 3) * 8192;
        uint32_t aS = aB + so, wS = wB + so;
#pragma unroll
        for (int kk = 0; kk < 2; kk++) {
            uint32_t a[4][4];
#pragma unroll
            for (int mi = 0; mi < 4; mi++)
                LDSM4(a[mi][0], a[mi][1], a[mi][2], a[mi][3],
                      aS + rowA[mi] * 64 + (((2 * kk + lhi) ^ xrA[mi]) << 4));
#pragma unroll
            for (int ng = 0; ng < 2; ng++) {
                uint32_t b0, b1, b2, b3;
                LDSM4(b0, b1, b2, b3,
                      wS + rowW[ng] * 64 + (((2 * kk + lhi) ^ xrW[ng]) << 4));
#pragma unroll
                for (int mi = 0; mi < 4; mi++) {
                    MMAH(oacc[mi][2 * ng], a[mi][0], a[mi][1], a[mi][2], a[mi][3], b0, b2);
                    MMAH(oacc[mi][2 * ng + 1], a[mi][0], a[mi][1], a[mi][2], a[mi][3], b1, b3);
                }
            }
        }
        __syncthreads();
    }

    int gid = lane >> 2, tig = lane & 3;
    int sel = n0 >> 8;
    float qs = (MODE == 1 && sel <= 1) ? QS2 : 1.0f;
#pragma unroll
    for (int mi = 0; mi < 4; mi++) {
        int row0 = m0 + wm * 64 + mi * 16 + gid;
#pragma unroll
        for (int nj = 0; nj < 4; nj++) {
            int colw = wn * 32 + nj * 8 + tig * 2;
            float b0 = 0.f, b1 = 0.f;
            if (MODE == 1) { b0 = bias[n0 + colw]; b1 = bias[n0 + colw + 1]; }
            float v00 = (oacc[mi][nj][0] + b0) * qs, v01 = (oacc[mi][nj][1] + b1) * qs;
            float v10 = (oacc[mi][nj][2] + b0) * qs, v11 = (oacc[mi][nj][3] + b1) * qs;
            if (MODE == 0) {
                float* Cp = (float*)C0 + (size_t)z * MROWS * DIM;
                *(float2*)(Cp + (size_t)row0 * N + n0 + colw) = make_float2(v00, v01);
                *(float2*)(Cp + (size_t)(row0 + 8) * N + n0 + colw) = make_float2(v10, v11);
            } else {
                int col = (n0 & 255) + colw;
                if (sel <= 1) {
                    uint8_t* dst = (uint8_t*)(sel == 0 ? C0 : C1) + (size_t)z * MROWS * DIM;
                    uint16_t p0, p1;
                    CVTE4(p0, v00, v01);
                    CVTE4(p1, v10, v11);
                    *(uint16_t*)(dst + (size_t)row0 * DIM + col) = p0;
                    *(uint16_t*)(dst + (size_t)(row0 + 8) * DIM + col) = p1;
                } else {
                    __half* dst = (__half*)C2 + (size_t)z * MROWS * DIM;
                    *(__half2*)(dst + (size_t)row0 * DIM + col) = __floats2half2_rn(v00, v01);
                    *(__half2*)(dst + (size_t)(row0 + 8) * DIM + col) = __floats2half2_rn(v10, v11);
                }
            }
        }
    }
}

// ================== split-K reduce -> d_out ================================
__global__ void __launch_bounds__(256) kan_reduce(float* __restrict__ out) {
    size_t i = ((size_t)blockIdx.x * 256 + threadIdx.x) * 4;
    float4 a = *(float4*)(g_Kp + i);
    float4 b = *(float4*)(g_Kp + (size_t)MROWS * DIM + i);
    *(float4*)(out + i) = make_float4(a.x + b.x, a.y + b.y, a.z + b.z, a.w + b.w);
}

// ================== packers ================================================
__global__ void __launch_bounds__(256) tok2half(const float* __restrict__ t0,
                                                const float* __restrict__ t1,
                                                const float* __restrict__ t2) {
    size_t i = (size_t)blockIdx.x * 256 + threadIdx.x;
    size_t n = (size_t)MROWS * DIM / 4;
    const float4* src = i < n ? (const float4*)t0 : (i < 2 * n ? (const float4*)t1 : (const float4*)t2);
    float4 v = src[i % n];
    *(__half2*)(g_T16 + i * 4) = __floats2half2_rn(v.x, v.y);
    *(__half2*)(g_T16 + i * 4 + 2) = __floats2half2_rn(v.z, v.w);
}

__global__ void __launch_bounds__(256) pack_wqkv(const float* __restrict__ wq, const float* __restrict__ bq,
                                                 const float* __restrict__ wk, const float* __restrict__ bk,
                                                 const float* __restrict__ wv, const float* __restrict__ bv) {
    int o = blockIdx.x;
    int k = threadIdx.x;
    int sel = o >> 8, oo = o & 255;
    const float* wsrc = sel == 0 ? wq : (sel == 1 ? wk : wv);
    g_Wqkv[(size_t)o * DIM + k] = __float2half(wsrc[(size_t)oo * DIM + k]);
    if (k == 0) {
        const float* bsrc = sel == 0 ? bq : (sel == 1 ? bk : bv);
        g_bqkv[o] = bsrc[oo];
    }
}

__global__ void __launch_bounds__(256) wcombine_kernel(const float* __restrict__ bw,
                                                       const float* __restrict__ sw,
                                                       const float* __restrict__ ss) {
    int k = blockIdx.x * 256 + threadIdx.x;
    int o = blockIdx.y;
    float w;
    if (k < IN_F) {
        w = bw[(size_t)o * IN_F + k];
    } else {
        int kk = k - IN_F;
        int i = kk >> 3, f = kk & 7;
        w = sw[((size_t)o * IN_F + i) * 8 + f] * ss[(size_t)o * IN_F + i];
    }
    g_Wh[(size_t)o * KEXP + k] = __float2half(w);
}

// ====== flash attention: fp8 QK^T (m16n8k32 e4m3) + fp16 PV, split-KV(3) ===
// smem: Q8 32KB @0, K8 2x16KB @32768, V fp16 2x32KB @65536 -> 128KB.
#define FMM_SMEM 131072
#define SK8O 32768
#define SVO  65536

__global__ void __launch_bounds__(256, 1) flash_mma_kernel() {
    extern __shared__ char sm[];
    uint32_t sb = smem_u32(sm);
    int tid = threadIdx.x, lane = tid & 31, w = tid >> 5;
    int lrow = lane & 7, lhalf = (lane >> 3) & 1, lhi = lane >> 4;
    int vw = blockIdx.y >> 1, bt = blockIdx.y & 1, q0 = blockIdx.x << 7;
    int z = blockIdx.z;
    int k0 = z == 0 ? 0 : (z == 1 ? 22 : 43);
    int k1 = z == 0 ? 22 : (z == 1 ? 43 : 64);
    int nkt = k1 - k0;
    size_t rowidx = (size_t)vw * MROWS + (size_t)bt * S_LEN;

    // load Q8 [128 rows x 256B], swizzled 16B chunks (16 chunks/row)
    {
        const uint4* Qg = (const uint4*)(g_Q8 + (rowidx + q0) * DIM);
#pragma unroll
        for (int it = 0; it < 8; it++) {
            int idx = tid + it * 256;
            int r = idx >> 4, c = idx & 15;
            *(uint4*)(sm + r * 256 + ((c ^ (r & 7)) << 4)) = Qg[idx];
        }
    }

    // cp.async dst offsets: K8 (256B rows), V (512B rows)
    uint32_t dK[4], dV[8];
#pragma unroll
    for (int it = 0; it < 4; it++) {
        int idx = tid + it * 256;
        int r = idx >> 4, c = idx & 15;
        dK[it] = r * 256 + ((c ^ (r & 7)) << 4);
    }
#pragma unroll
    for (int it = 0; it < 8; it++) {
        int idx = tid + it * 256;
        int r = idx >> 5, c = idx & 31;
        dV[it] = r * 512 + ((c ^ (r & 7)) << 4);
    }
    auto issue = [&](int kt, int buf) {
        const char* Kg = (const char*)(g_K8 + (rowidx + (size_t)kt * 64) * DIM);
        const char* Vg = (const char*)(g_Vb + (rowidx + (size_t)kt * 64) * DIM);
        uint32_t kb = sb + SK8O + buf * 16384, vb = sb + SVO + buf * 32768;
#pragma unroll
        for (int it = 0; it < 4; it++)
            CPA16(kb + dK[it], Kg + (size_t)(tid + it * 256) * 16);
#pragma unroll
        for (int it = 0; it < 8; it++)
            CPA16(vb + dV[it], Vg + (size_t)(tid + it * 256) * 16);
    };

    uint32_t qrowbase = sb + (uint32_t)(w * 16 + lrow + (lhalf << 3)) * 256;
    uint32_t krel[4], vrel[4];
#pragma unroll
    for (int t = 0; t < 4; t++) {
        krel[t] = (uint32_t)(t * 16 + lrow + (lhalf << 3)) * 256;
        vrel[t] = (uint32_t)(t * 16 + lrow + (lhalf << 3)) * 512;
    }

    float oacc[32][4];
#pragma unroll
    for (int i = 0; i < 32; i++)
#pragma unroll
        for (int j = 0; j < 4; j++) oacc[i][j] = 0.0f;
    float lsum0 = 0.0f, lsum1 = 0.0f;

    issue(k0, 0);
    CPCOMMIT();

    for (int i = 0; i < nkt; i++) {
        int cur = i & 1;
        if (i + 1 < nkt) {
            issue(k0 + i + 1, 1 - cur);
            CPCOMMIT();
            CPWAIT1();
        } else {
            CPWAIT0();
        }
        __syncthreads();

        uint32_t kS = sb + SK8O + cur * 16384, vS = sb + SVO + cur * 32768;

        // ---- S = Q @ K^T in e4m3, k32 steps (8 over D=256) ----
        float sacc[8][4];
#pragma unroll
        for (int ii = 0; ii < 8; ii++)
#pragma unroll
            for (int j = 0; j < 4; j++) sacc[ii][j] = 0.0f;
#pragma unroll
        for (int ks = 0; ks < 8; ks++) {
            uint32_t chq = (uint32_t)(((2 * ks + lhi) ^ lrow) << 4);
            uint32_t a0, a1, a2, a3;
            LDSM4(a0, a1, a2, a3, qrowbase + chq);
#pragma unroll
            for (int kb = 0; kb < 4; kb++) {
                uint32_t b0, b1, b2, b3;
                LDSM4(b0, b1, b2, b3, kS + krel[kb] + chq);
                MMAF8(sacc[2 * kb], a0, a1, a2, a3, b0, b2);
                MMAF8(sacc[2 * kb + 1], a0, a1, a2, a3, b1, b3);
            }
        }

        // ---- per-kc: P = ex2(S) fp16x2, O += P @ V (fp16 mma) ----
        __half2 hs0 = __floats2half2_rn(0.f, 0.f);
        __half2 hs1 = hs0;
#pragma unroll
        for (int kc = 0; kc < 4; kc++) {
            uint32_t pa[4];
#pragma unroll
            for (int jj = 0; jj < 2; jj++) {
                int j = 2 * kc + jj;
                __half2 t01 = __floats2half2_rn(sacc[j][0], sacc[j][1]);
                __half2 t23 = __floats2half2_rn(sacc[j][2], sacc[j][3]);
                uint32_t p01, p23;
                EX2H2(p01, *(uint32_t*)&t01);
                EX2H2(p23, *(uint32_t*)&t23);
                pa[2 * jj] = p01;
                pa[2 * jj + 1] = p23;
                hs0 = __hadd2(hs0, *(__half2*)&p01);
                hs1 = __hadd2(hs1, *(__half2*)&p23);
            }
#pragma unroll
            for (int nn = 0; nn < 16; nn++) {
                uint32_t r0, r1, r2, r3;
                LDSM4T(r0, r1, r2, r3, vS + vrel[kc] + (((2 * nn + lhi) ^ lrow) << 4));
                MMAH(oacc[2 * nn], pa[0], pa[1], pa[2], pa[3], r0, r1);
                MMAH(oacc[2 * nn + 1], pa[0], pa[1], pa[2], pa[3], r2, r3);
            }
        }
        float2 f0 = __half22float2(hs0);
        float2 f1 = __half22float2(hs1);
        lsum0 += f0.x + f0.y;
        lsum1 += f1.x + f1.y;
        __syncthreads();
    }

    lsum0 += __shfl_xor_sync(0xffffffffu, lsum0, 1);
    lsum0 += __shfl_xor_sync(0xffffffffu, lsum0, 2);
    lsum1 += __shfl_xor_sync(0xffffffffu, lsum1, 1);
    lsum1 += __shfl_xor_sync(0xffffffffu, lsum1, 2);
    int gid = lane >> 2, tig = lane & 3;
    int row0 = q0 + (w << 4) + gid;
    if (tig == 0) {
        g_L[z * NROWS + rowidx + row0] = lsum0;
        g_L[z * NROWS + rowidx + row0 + 8] = lsum1;
    }
    float* o0 = g_Ap + (size_t)z * PIECE + (rowidx + row0) * DIM;
    float* o1 = o0 + 8 * DIM;
#pragma unroll
    for (int nt = 0; nt < 32; nt++) {
        int col = nt * 8 + tig * 2;
        *(float2*)(o0 + col) = make_float2(oacc[nt][0], oacc[nt][1]);
        *(float2*)(o1 + col) = make_float2(oacc[nt][2], oacc[nt][3]);
    }
}

// ====== fused: merge KV pieces + residual + LN + silu/spline expand ========
__global__ void __launch_bounds__(256) resid_ln_expand_kernel(
    const float* __restrict__ t0, const float* __restrict__ t1, const float* __restrict__ t2,
    const float* __restrict__ s0, const float* __restrict__ b0,
    const float* __restrict__ s1, const float* __restrict__ b1,
    const float* __restrict__ s2, const float* __restrict__ b2) {
    __shared__ float ps[16];
    int r = blockIdx.x, v = blockIdx.y, c = threadIdx.x;
    int lane = c & 31, wid = c >> 5;
    const float* tok = v == 0 ? t0 : (v == 1 ? t1 : t2);
    const float* sc = v == 0 ? s0 : (v == 1 ? s1 : s2);
    const float* bi = v == 0 ? b0 : (v == 1 ? b1 : b2);
    size_t row = (size_t)v * MROWS + r;
    float l = g_L[row] + g_L[NROWS + row] + g_L[2 * NROWS + row];
    size_t e = row * DIM + c;
    float o = g_Ap[e] + g_Ap[PIECE + e] + g_Ap[2 * PIECE + e];
    float a = o / l + tok[(size_t)r * DIM + c];
    float s1v = a, s2v = a * a;
#pragma unroll
    for (int off = 16; off > 0; off >>= 1) {
        s1v += __shfl_xor_sync(0xffffffffu, s1v, off);
        s2v += __shfl_xor_sync(0xffffffffu, s2v, off);
    }
    if (lane == 0) { ps[wid] = s1v; ps[8 + wid] = s2v; }
    __syncthreads();
    float t1s = 0.f, t2s = 0.f;
#pragma unroll
    for (int q = 0; q < 8; q++) { t1s += ps[q]; t2s += ps[8 + q]; }
    float mu = t1s * (1.0f / 256.0f);
    float var = t2s * (1.0f / 256.0f) - mu * mu;
    float x = (a - mu) * rsqrtf(var + 1e-5f) * sc[c] + bi[c];

    int i = v * DIM + c;
    __half* Ar = g_Ah + (size_t)r * KEXP;
    Ar[i] = __float2half(x / (1.0f + expf(-x)));
    float g[12];
#pragma unroll
    for (int j = 0; j < 12; j++) g[j] = (float)(j - 3) * 0.4f + (-1.0f);
    float b[11];
#pragma unroll
    for (int t = 0; t < 11; t++) b[t] = (x >= g[t] && x < g[t + 1]) ? 1.0f : 0.0f;
#pragma unroll
    for (int k = 1; k <= 3; k++) {
#pragma unroll
        for (int t = 0; t + k < 11; t++)
            b[t] = (x - g[t]) / (g[t + k] - g[t]) * b[t]
                 + (g[t + k + 1] - x) / (g[t + k + 1] - g[t + 1]) * b[t + 1];
    }
    __half2 h0 = __floats2half2_rn(b[0], b[1]);
    __half2 h1 = __floats2half2_rn(b[2], b[3]);
    __half2 h2 = __floats2half2_rn(b[4], b[5]);
    __half2 h3 = __floats2half2_rn(b[6], b[7]);
    uint4 pk = make_uint4(*(uint32_t*)&h0, *(uint32_t*)&h1, *(uint32_t*)&h2, *(uint32_t*)&h3);
    *(uint4*)(Ar + IN_F + (size_t)i * 8) = pk;
}

extern "C" void kernel_launch(void* const* d_in, const int* in_sizes, int n_in,
                              void* d_out, int out_size) {
    const float* ax = (const float*)d_in[0];
    const float* sg = (const float*)d_in[1];
    const float* co = (const float*)d_in[2];
    const float* wq = (const float*)d_in[3];
    const float* bq = (const float*)d_in[4];
    const float* wk = (const float*)d_in[5];
    const float* bk = (const float*)d_in[6];
    const float* wv = (const float*)d_in[7];
    const float* bv = (const float*)d_in[8];
    // d_in[9] = view_emb: softmax-invariant, unused.
    const float* lnS0 = (const float*)d_in[10];
    const float* lnB0 = (const float*)d_in[11];
    const float* lnS1 = (const float*)d_in[12];
    const float* lnB1 = (const float*)d_in[13];
    const float* lnS2 = (const float*)d_in[14];
    const float* lnB2 = (const float*)d_in[15];
    const float* bw = (const float*)d_in[16];
    const float* sw = (const float*)d_in[17];
    const float* ss = (const float*)d_in[18];
    float* out = (float*)d_out;

    __half *Vp, *Tp, *Wqkvp, *Ahp, *Whp;
    uint8_t *Qp, *Kp;
    float *bqkvp, *Kpp;
    cudaGetSymbolAddress((void**)&Qp, g_Q8);
    cudaGetSymbolAddress((void**)&Kp, g_K8);
    cudaGetSymbolAddress((void**)&Vp, g_Vb);
    cudaGetSymbolAddress((void**)&Tp, g_T16);
    cudaGetSymbolAddress((void**)&Wqkvp, g_Wqkv);
    cudaGetSymbolAddress((void**)&bqkvp, g_bqkv);
    cudaGetSymbolAddress((void**)&Ahp, g_Ah);
    cudaGetSymbolAddress((void**)&Whp, g_Wh);
    cudaGetSymbolAddress((void**)&Kpp, g_Kp);
    cudaFuncSetAttribute(flash_mma_kernel, cudaFuncAttributeMaxDynamicSharedMemorySize, FMM_SMEM);

    tok2half<<<3 * MROWS * DIM / 4 / 256, 256>>>(ax, sg, co);
    pack_wqkv<<<768, 256>>>(wq, bq, wk, bk, wv, bv);
    wcombine_kernel<<<dim3(KEXP / 256, DIM), 256>>>(bw, sw, ss);

    hgemm<1><<<dim3(6, 64, 3), 256>>>(Tp, Wqkvp, bqkvp, Qp, Kp, Vp, MROWS, 768, DIM, DIM);

    flash_mma_kernel<<<dim3(32, 6, 3), 256, FMM_SMEM>>>();

    resid_ln_expand_kernel<<<dim3(MROWS, 3), 256>>>(ax, sg, co, lnS0, lnB0, lnS1, lnB1, lnS2, lnB2);

    hgemm<0><<<dim3(2, 64, 2), 256>>>(Ahp, Whp, (const float*)0, Kpp, (void*)0, (void*)0,
                                      MROWS, DIM, KEXP, KEXP / 2);
    kan_reduce<<<MROWS * DIM / 4 / 256, 256>>>(out);
}

// round 13
// speedup vs baseline: 1.0199x; 1.0199x over previous
#include <cuda_runtime.h>
#include <cuda_fp16.h>
#include <math.h>
#include <cstdint>

#define S_LEN 4096
#define DIM   256
#define MROWS 8192
#define IN_F  768
#define KEXP  6912
#define PIECE (3ull * MROWS * DIM)
#define NROWS (3 * MROWS)
#define QSCALE 0.09016844f   // log2(e)/16

__device__ __half g_Ah[(size_t)MROWS * KEXP];
__device__ __half g_Wh[(size_t)DIM * KEXP];
__device__ __half g_T16[3ull * MROWS * DIM];
__device__ __half g_Wqkv[768ull * DIM];
__device__ float  g_bqkv[768];
__device__ __half g_Qb[3ull * MROWS * DIM];
__device__ __half g_Kb[3ull * MROWS * DIM];
__device__ __half g_Vb[3ull * MROWS * DIM];
__device__ float g_Ap[3ull * PIECE];
__device__ float g_L[3 * NROWS];
__device__ float g_Kp[2ull * MROWS * DIM];

// ======================= PTX helpers (baseline sm_103) =====================
__device__ __forceinline__ uint32_t smem_u32(const void* p) {
    uint32_t a;
    asm("{ .reg .u64 t; cvta.to.shared.u64 t, %1; cvt.u32.u64 %0, t; }" : "=r"(a) : "l"(p));
    return a;
}
#define LDSM4(d0, d1, d2, d3, a)                                                        \
    asm volatile("ldmatrix.sync.aligned.m8n8.x4.shared.b16 {%0,%1,%2,%3}, [%4];"        \
                 : "=r"(d0), "=r"(d1), "=r"(d2), "=r"(d3) : "r"(a))
#define LDSM4T(d0, d1, d2, d3, a)                                                       \
    asm volatile("ldmatrix.sync.aligned.m8n8.x4.trans.shared.b16 {%0,%1,%2,%3}, [%4];"  \
                 : "=r"(d0), "=r"(d1), "=r"(d2), "=r"(d3) : "r"(a))
#define MMAH(c, a0, a1, a2, a3, b0, b1)                                                 \
    asm volatile("mma.sync.aligned.m16n8k16.row.col.f32.f16.f16.f32 "                   \
                 "{%0,%1,%2,%3}, {%4,%5,%6,%7}, {%8,%9}, {%0,%1,%2,%3};"                \
                 : "+f"((c)[0]), "+f"((c)[1]), "+f"((c)[2]), "+f"((c)[3])               \
                 : "r"(a0), "r"(a1), "r"(a2), "r"(a3), "r"(b0), "r"(b1))
#define CPA16(d, s) asm volatile("cp.async.cg.shared.global [%0], [%1], 16;" :: "r"(d), "l"(s))
#define CPCOMMIT()  asm volatile("cp.async.commit_group;" ::: "memory")
#define CPWAIT2()   asm volatile("cp.async.wait_group 2;" ::: "memory")
#define CPWAIT1()   asm volatile("cp.async.wait_group 1;" ::: "memory")
#define CPWAIT0()   asm volatile("cp.async.wait_group 0;" ::: "memory")
#define EX2H2(d, s) asm("ex2.approx.f16x2 %0, %1;" : "=r"(d) : "r"(s))

// ================== HMMA GEMM: C[M,N] = A[M,K] @ W[N,K]^T ==================
// BM=128, BN=128, BK=32, 256 thr, 3-stage cp.async.
// MODE 0: KAN split-K (z = K-piece, fp32 partial out).
// MODE 1: QKV (z = view; fp16 out split q/k/v by col>>8; Q pre-scaled).
template <int MODE>
__global__ void __launch_bounds__(256) hgemm(const __half* __restrict__ A,
                                             const __half* __restrict__ W,
                                             const float* __restrict__ bias,
                                             void* __restrict__ C0,
                                             void* __restrict__ C1,
                                             void* __restrict__ C2,
                                             int M, int N, int Kst, int Klen) {
    __shared__ __align__(16) char sA[3][8192];
    __shared__ __align__(16) char sW[3][8192];
    uint32_t aB = smem_u32(sA), wB = smem_u32(sW);
    int tid = threadIdx.x, lane = tid & 31, w = tid >> 5;
    int wm = w >> 2, wn = w & 3;
    int m0 = blockIdx.y << 7, n0 = blockIdx.x << 7;
    int z = blockIdx.z;
    int lrow = lane & 7, lhalf = (lane >> 3) & 1, lhi = lane >> 4;

    const __half* Ab = (MODE == 0) ? A + (size_t)z * Klen : A + (size_t)z * MROWS * DIM;
    const __half* Wb = (MODE == 0) ? W + (size_t)z * Klen : W;

    int r0 = tid >> 2, c0 = tid & 3;
    int r1 = (tid + 256) >> 2, c1 = (tid + 256) & 3;
    uint32_t dA0 = r0 * 64 + ((c0 ^ ((r0 >> 1) & 3)) << 4);
    uint32_t dA1 = r1 * 64 + ((c1 ^ ((r1 >> 1) & 3)) << 4);
    const __half* As0 = Ab + (size_t)(m0 + r0) * Kst + c0 * 8;
    const __half* As1 = Ab + (size_t)(m0 + r1) * Kst + c1 * 8;
    const __half* Ws0 = Wb + (size_t)(n0 + r0) * Kst + c0 * 8;
    const __half* Ws1 = Wb + (size_t)(n0 + r1) * Kst + c1 * 8;

    int rowA[4], xrA[4];
#pragma unroll
    for (int mi = 0; mi < 4; mi++) {
        rowA[mi] = wm * 64 + mi * 16 + lrow + (lhalf << 3);
        xrA[mi] = (rowA[mi] >> 1) & 3;
    }
    int rowW[2], xrW[2];
#pragma unroll
    for (int ng = 0; ng < 2; ng++) {
        rowW[ng] = wn * 32 + ng * 16 + lrow + (lhalf << 3);
        xrW[ng] = (rowW[ng] >> 1) & 3;
    }

    float oacc[4][4][4];
#pragma unroll
    for (int i = 0; i < 4; i++)
#pragma unroll
        for (int j = 0; j < 4; j++)
#pragma unroll
            for (int e = 0; e < 4; e++) oacc[i][j][e] = 0.0f;

    int KT = Klen >> 5;
    auto issue = [&](int kt) {
        uint32_t so = (uint32_t)(kt % 3) * 8192;
        int nk = kt << 5;
        CPA16(aB + so + dA0, As0 + nk); CPA16(aB + so + dA1, As1 + nk);
        CPA16(wB + so + dA0, Ws0 + nk); CPA16(wB + so + dA1, Ws1 + nk);
        CPCOMMIT();
    };
    issue(0);
    issue(1);

    for (int kt = 0; kt < KT; kt++) {
        if (kt + 2 < KT) { issue(kt + 2); CPWAIT2(); }
        else if (kt + 1 < KT) { CPWAIT1(); }
        else { CPWAIT0(); }
        __syncthreads();
        uint32_t so = (uint32_t)(kt % 3) * 8192;
        uint32_t aS = aB + so, wS = wB + so;
#pragma unroll
        for (int kk = 0; kk < 2; kk++) {
            uint32_t a[4][4];
#pragma unroll
            for (int mi = 0; mi < 4; mi++)
                LDSM4(a[mi][0], a[mi][1], a[mi][2], a[mi][3],
                      aS + rowA[mi] * 64 + (((2 * kk + lhi) ^ xrA[mi]) << 4));
#pragma unroll
            for (int ng = 0; ng < 2; ng++) {
                uint32_t b0, b1, b2, b3;
                LDSM4(b0, b1, b2, b3,
                      wS + rowW[ng] * 64 + (((2 * kk + lhi) ^ xrW[ng]) << 4));
#pragma unroll
                for (int mi = 0; mi < 4; mi++) {
                    MMAH(oacc[mi][2 * ng], a[mi][0], a[mi][1], a[mi][2], a[mi][3], b0, b2);
                    MMAH(oacc[mi][2 * ng + 1], a[mi][0], a[mi][1], a[mi][2], a[mi][3], b1, b3);
                }
            }
        }
        __syncthreads();
    }

    int gid = lane >> 2, tig = lane & 3;
    float qs = (MODE == 1 && (n0 >> 8) == 0) ? QSCALE : 1.0f;
#pragma unroll
    for (int mi = 0; mi < 4; mi++) {
        int row0 = m0 + wm * 64 + mi * 16 + gid;
#pragma unroll
        for (int nj = 0; nj < 4; nj++) {
            int colw = wn * 32 + nj * 8 + tig * 2;
            float b0 = 0.f, b1 = 0.f;
            if (MODE == 1) { b0 = bias[n0 + colw]; b1 = bias[n0 + colw + 1]; }
            float v00 = (oacc[mi][nj][0] + b0) * qs, v01 = (oacc[mi][nj][1] + b1) * qs;
            float v10 = (oacc[mi][nj][2] + b0) * qs, v11 = (oacc[mi][nj][3] + b1) * qs;
            if (MODE == 0) {
                float* Cp = (float*)C0 + (size_t)z * MROWS * DIM;
                *(float2*)(Cp + (size_t)row0 * N + n0 + colw) = make_float2(v00, v01);
                *(float2*)(Cp + (size_t)(row0 + 8) * N + n0 + colw) = make_float2(v10, v11);
            } else {
                int sel = n0 >> 8;
                __half* dst = (__half*)(sel == 0 ? C0 : (sel == 1 ? C1 : C2)) + (size_t)z * MROWS * DIM;
                int col = (n0 & 255) + colw;
                *(__half2*)(dst + (size_t)row0 * DIM + col) = __floats2half2_rn(v00, v01);
                *(__half2*)(dst + (size_t)(row0 + 8) * DIM + col) = __floats2half2_rn(v10, v11);
            }
        }
    }
}

// ================== split-K reduce -> d_out ================================
__global__ void __launch_bounds__(256) kan_reduce(float* __restrict__ out) {
    size_t i = ((size_t)blockIdx.x * 256 + threadIdx.x) * 4;
    float4 a = *(float4*)(g_Kp + i);
    float4 b = *(float4*)(g_Kp + (size_t)MROWS * DIM + i);
    *(float4*)(out + i) = make_float4(a.x + b.x, a.y + b.y, a.z + b.z, a.w + b.w);
}

// ================== packers ================================================
__global__ void __launch_bounds__(256) tok2half(const float* __restrict__ t0,
                                                const float* __restrict__ t1,
                                                const float* __restrict__ t2) {
    size_t i = (size_t)blockIdx.x * 256 + threadIdx.x;
    size_t n = (size_t)MROWS * DIM / 4;
    const float4* src = i < n ? (const float4*)t0 : (i < 2 * n ? (const float4*)t1 : (const float4*)t2);
    float4 v = src[i % n];
    *(__half2*)(g_T16 + i * 4) = __floats2half2_rn(v.x, v.y);
    *(__half2*)(g_T16 + i * 4 + 2) = __floats2half2_rn(v.z, v.w);
}

__global__ void __launch_bounds__(256) pack_wqkv(const float* __restrict__ wq, const float* __restrict__ bq,
                                                 const float* __restrict__ wk, const float* __restrict__ bk,
                                                 const float* __restrict__ wv, const float* __restrict__ bv) {
    int o = blockIdx.x;
    int k = threadIdx.x;
    int sel = o >> 8, oo = o & 255;
    const float* wsrc = sel == 0 ? wq : (sel == 1 ? wk : wv);
    g_Wqkv[(size_t)o * DIM + k] = __float2half(wsrc[(size_t)oo * DIM + k]);
    if (k == 0) {
        const float* bsrc = sel == 0 ? bq : (sel == 1 ? bk : bv);
        g_bqkv[o] = bsrc[oo];
    }
}

__global__ void __launch_bounds__(256) wcombine_kernel(const float* __restrict__ bw,
                                                       const float* __restrict__ sw,
                                                       const float* __restrict__ ss) {
    int k = blockIdx.x * 256 + threadIdx.x;
    int o = blockIdx.y;
    float w;
    if (k < IN_F) {
        w = bw[(size_t)o * IN_F + k];
    } else {
        int kk = k - IN_F;
        int i = kk >> 3, f = kk & 7;
        w = sw[((size_t)o * IN_F + i) * 8 + f] * ss[(size_t)o * IN_F + i];
    }
    g_Wh[(size_t)o * KEXP + k] = __float2half(w);
}

// ============ HMMA flash attention, split-KV(3), cp.async x2 ===============
// Q pre-scaled by log2(e)/16 -> P = ex2(S) directly; Q fragments hoisted
// into registers once (loop-invariant) to cut S-phase LDSM by 20%.
#define FMM_SMEM 196608
#define SKO 65536
#define SVO 131072

__global__ void __launch_bounds__(256, 1) flash_mma_kernel() {
    extern __shared__ char sm[];
    uint32_t sb = smem_u32(sm);
    int tid = threadIdx.x, lane = tid & 31, w = tid >> 5;
    int lrow = lane & 7, lhalf = (lane >> 3) & 1, lhi = lane >> 4;
    int vw = blockIdx.y >> 1, bt = blockIdx.y & 1, q0 = blockIdx.x << 7;
    int z = blockIdx.z;
    int k0 = z == 0 ? 0 : (z == 1 ? 22 : 43);
    int k1 = z == 0 ? 22 : (z == 1 ? 43 : 64);
    int nkt = k1 - k0;
    size_t rowidx = (size_t)vw * MROWS + (size_t)bt * S_LEN;

    {
        const uint4* Qg = (const uint4*)(g_Qb + (rowidx + q0) * DIM);
#pragma unroll
        for (int it = 0; it < 16; it++) {
            int idx = tid + it * 256;
            int r = idx >> 5, c = idx & 31;
            *(uint4*)(sm + r * 512 + ((c ^ (r & 7)) << 4)) = Qg[idx];
        }
    }

    uint32_t dsto[8];
#pragma unroll
    for (int it = 0; it < 8; it++) {
        int idx = tid + it * 256;
        int r = idx >> 5, c = idx & 31;
        dsto[it] = r * 512 + ((c ^ (r & 7)) << 4);
    }
    auto issue = [&](int kt, int buf) {
        const char* Kg = (const char*)(g_Kb + (rowidx + (size_t)kt * 64) * DIM);
        const char* Vg = (const char*)(g_Vb + (rowidx + (size_t)kt * 64) * DIM);
        uint32_t kb = sb + SKO + buf * 32768, vb = sb + SVO + buf * 32768;
#pragma unroll
        for (int it = 0; it < 8; it++) {
            size_t so = (size_t)(tid + it * 256) * 16;
            CPA16(kb + dsto[it], Kg + so);
            CPA16(vb + dsto[it], Vg + so);
        }
    };

    issue(k0, 0);
    CPCOMMIT();

    // ---- hoist Q fragments into registers (loop-invariant) ----
    __syncthreads();   // Q stores (all threads) -> Q ldmatrix reads
    uint32_t qbase = sb + ((w << 4) + lrow + (lhalf << 3)) * 512;
    uint32_t qa[16][4];
#pragma unroll
    for (int ks = 0; ks < 16; ks++) {
        uint32_t chq = (uint32_t)(((2 * ks + lhi) ^ lrow) << 4);
        LDSM4(qa[ks][0], qa[ks][1], qa[ks][2], qa[ks][3], qbase + chq);
    }

    uint32_t rroff[4];
#pragma unroll
    for (int t = 0; t < 4; t++)
        rroff[t] = (t * 16 + lrow + (lhalf << 3)) * 512;

    float oacc[32][4];
#pragma unroll
    for (int i = 0; i < 32; i++)
#pragma unroll
        for (int j = 0; j < 4; j++) oacc[i][j] = 0.0f;
    float lsum0 = 0.0f, lsum1 = 0.0f;

    for (int i = 0; i < nkt; i++) {
        int cur = i & 1;
        if (i + 1 < nkt) {
            issue(k0 + i + 1, 1 - cur);
            CPCOMMIT();
            CPWAIT1();
        } else {
            CPWAIT0();
        }
        __syncthreads();

        uint32_t kS = sb + SKO + cur * 32768, vS = sb + SVO + cur * 32768;

        // ---- S = Q @ K^T (pre-scaled into log2 domain) ----
        float sacc[8][4];
#pragma unroll
        for (int ii = 0; ii < 8; ii++)
#pragma unroll
            for (int j = 0; j < 4; j++) sacc[ii][j] = 0.0f;
#pragma unroll
        for (int ks = 0; ks < 16; ks++) {
            uint32_t chq = (uint32_t)(((2 * ks + lhi) ^ lrow) << 4);
#pragma unroll
            for (int kb = 0; kb < 4; kb++) {
                uint32_t b0, b1, b2, b3;
                LDSM4(b0, b1, b2, b3, kS + rroff[kb] + chq);
                MMAH(sacc[2 * kb], qa[ks][0], qa[ks][1], qa[ks][2], qa[ks][3], b0, b2);
                MMAH(sacc[2 * kb + 1], qa[ks][0], qa[ks][1], qa[ks][2], qa[ks][3], b1, b3);
            }
        }

        // ---- per-kc: P = ex2(S) in fp16x2, then O += P @ V ----
        __half2 hs0 = __floats2half2_rn(0.f, 0.f);
        __half2 hs1 = hs0;
#pragma unroll
        for (int kc = 0; kc < 4; kc++) {
            uint32_t pa[4];
#pragma unroll
            for (int jj = 0; jj < 2; jj++) {
                int j = 2 * kc + jj;
                __half2 t01 = __floats2half2_rn(sacc[j][0], sacc[j][1]);
                __half2 t23 = __floats2half2_rn(sacc[j][2], sacc[j][3]);
                uint32_t p01, p23;
                EX2H2(p01, *(uint32_t*)&t01);
                EX2H2(p23, *(uint32_t*)&t23);
                pa[2 * jj] = p01;
                pa[2 * jj + 1] = p23;
                hs0 = __hadd2(hs0, *(__half2*)&p01);
                hs1 = __hadd2(hs1, *(__half2*)&p23);
            }
#pragma unroll
            for (int nn = 0; nn < 16; nn++) {
                uint32_t r0, r1, r2, r3;
                LDSM4T(r0, r1, r2, r3, vS + rroff[kc] + (((2 * nn + lhi) ^ lrow) << 4));
                MMAH(oacc[2 * nn], pa[0], pa[1], pa[2], pa[3], r0, r1);
                MMAH(oacc[2 * nn + 1], pa[0], pa[1], pa[2], pa[3], r2, r3);
            }
        }
        float2 f0 = __half22float2(hs0);
        float2 f1 = __half22float2(hs1);
        lsum0 += f0.x + f0.y;
        lsum1 += f1.x + f1.y;
        __syncthreads();
    }

    lsum0 += __shfl_xor_sync(0xffffffffu, lsum0, 1);
    lsum0 += __shfl_xor_sync(0xffffffffu, lsum0, 2);
    lsum1 += __shfl_xor_sync(0xffffffffu, lsum1, 1);
    lsum1 += __shfl_xor_sync(0xffffffffu, lsum1, 2);
    int gid = lane >> 2, tig = lane & 3;
    int row0 = q0 + (w << 4) + gid;
    if (tig == 0) {
        g_L[z * NROWS + rowidx + row0] = lsum0;
        g_L[z * NROWS + rowidx + row0 + 8] = lsum1;
    }
    float* o0 = g_Ap + (size_t)z * PIECE + (rowidx + row0) * DIM;
    float* o1 = o0 + 8 * DIM;
#pragma unroll
    for (int nt = 0; nt < 32; nt++) {
        int col = nt * 8 + tig * 2;
        *(float2*)(o0 + col) = make_float2(oacc[nt][0], oacc[nt][1]);
        *(float2*)(o1 + col) = make_float2(oacc[nt][2], oacc[nt][3]);
    }
}

// ====== fused: merge KV pieces + residual + LN + silu/spline expand ========
__global__ void __launch_bounds__(256) resid_ln_expand_kernel(
    const float* __restrict__ t0, const float* __restrict__ t1, const float* __restrict__ t2,
    const float* __restrict__ s0, const float* __restrict__ b0,
    const float* __restrict__ s1, const float* __restrict__ b1,
    const float* __restrict__ s2, const float* __restrict__ b2) {
    __shared__ float ps[16];
    int r = blockIdx.x, v = blockIdx.y, c = threadIdx.x;
    int lane = c & 31, wid = c >> 5;
    const float* tok = v == 0 ? t0 : (v == 1 ? t1 : t2);
    const float* sc = v == 0 ? s0 : (v == 1 ? s1 : s2);
    const float* bi = v == 0 ? b0 : (v == 1 ? b1 : b2);
    size_t row = (size_t)v * MROWS + r;
    float l = g_L[row] + g_L[NROWS + row] + g_L[2 * NROWS + row];
    size_t e = row * DIM + c;
    float o = g_Ap[e] + g_Ap[PIECE + e] + g_Ap[2 * PIECE + e];
    float a = o / l + tok[(size_t)r * DIM + c];
    float s1v = a, s2v = a * a;
#pragma unroll
    for (int off = 16; off > 0; off >>= 1) {
        s1v += __shfl_xor_sync(0xffffffffu, s1v, off);
        s2v += __shfl_xor_sync(0xffffffffu, s2v, off);
    }
    if (lane == 0) { ps[wid] = s1v; ps[8 + wid] = s2v; }
    __syncthreads();
    float t1s = 0.f, t2s = 0.f;
#pragma unroll
    for (int q = 0; q < 8; q++) { t1s += ps[q]; t2s += ps[8 + q]; }
    float mu = t1s * (1.0f / 256.0f);
    float var = t2s * (1.0f / 256.0f) - mu * mu;
    float x = (a - mu) * rsqrtf(var + 1e-5f) * sc[c] + bi[c];

    int i = v * DIM + c;
    __half* Ar = g_Ah + (size_t)r * KEXP;
    Ar[i] = __float2half(x / (1.0f + expf(-x)));
    float g[12];
#pragma unroll
    for (int j = 0; j < 12; j++) g[j] = (float)(j - 3) * 0.4f + (-1.0f);
    float b[11];
#pragma unroll
    for (int t = 0; t < 11; t++) b[t] = (x >= g[t] && x < g[t + 1]) ? 1.0f : 0.0f;
#pragma unroll
    for (int k = 1; k <= 3; k++) {
#pragma unroll
        for (int t = 0; t + k < 11; t++)
            b[t] = (x - g[t]) / (g[t + k] - g[t]) * b[t]
                 + (g[t + k + 1] - x) / (g[t + k + 1] - g[t + 1]) * b[t + 1];
    }
    __half2 h0 = __floats2half2_rn(b[0], b[1]);
    __half2 h1 = __floats2half2_rn(b[2], b[3]);
    __half2 h2 = __floats2half2_rn(b[4], b[5]);
    __half2 h3 = __floats2half2_rn(b[6], b[7]);
    uint4 pk = make_uint4(*(uint32_t*)&h0, *(uint32_t*)&h1, *(uint32_t*)&h2, *(uint32_t*)&h3);
    *(uint4*)(Ar + IN_F + (size_t)i * 8) = pk;
}

extern "C" void kernel_launch(void* const* d_in, const int* in_sizes, int n_in,
                              void* d_out, int out_size) {
    const float* ax = (const float*)d_in[0];
    const float* sg = (const float*)d_in[1];
    const float* co = (const float*)d_in[2];
    const float* wq = (const float*)d_in[3];
    const float* bq = (const float*)d_in[4];
    const float* wk = (const float*)d_in[5];
    const float* bk = (const float*)d_in[6];
    const float* wv = (const float*)d_in[7];
    const float* bv = (const float*)d_in[8];
    // d_in[9] = view_emb: softmax-invariant, unused.
    const float* lnS0 = (const float*)d_in[10];
    const float* lnB0 = (const float*)d_in[11];
    const float* lnS1 = (const float*)d_in[12];
    const float* lnB1 = (const float*)d_in[13];
    const float* lnS2 = (const float*)d_in[14];
    const float* lnB2 = (const float*)d_in[15];
    const float* bw = (const float*)d_in[16];
    const float* sw = (const float*)d_in[17];
    const float* ss = (const float*)d_in[18];
    float* out = (float*)d_out;

    __half *Qp, *Kp, *Vp, *Tp, *Wqkvp, *Ahp, *Whp;
    float *bqkvp, *Kpp;
    cudaGetSymbolAddress((void**)&Qp, g_Qb);
    cudaGetSymbolAddress((void**)&Kp, g_Kb);
    cudaGetSymbolAddress((void**)&Vp, g_Vb);
    cudaGetSymbolAddress((void**)&Tp, g_T16);
    cudaGetSymbolAddress((void**)&Wqkvp, g_Wqkv);
    cudaGetSymbolAddress((void**)&bqkvp, g_bqkv);
    cudaGetSymbolAddress((void**)&Ahp, g_Ah);
    cudaGetSymbolAddress((void**)&Whp, g_Wh);
    cudaGetSymbolAddress((void**)&Kpp, g_Kp);
    cudaFuncSetAttribute(flash_mma_kernel, cudaFuncAttributeMaxDynamicSharedMemorySize, FMM_SMEM);

    tok2half<<<3 * MROWS * DIM / 4 / 256, 256>>>(ax, sg, co);
    pack_wqkv<<<768, 256>>>(wq, bq, wk, bk, wv, bv);
    wcombine_kernel<<<dim3(KEXP / 256, DIM), 256>>>(bw, sw, ss);

    hgemm<1><<<dim3(6, 64, 3), 256>>>(Tp, Wqkvp, bqkvp, Qp, Kp, Vp, MROWS, 768, DIM, DIM);

    flash_mma_kernel<<<dim3(32, 6, 3), 256, FMM_SMEM>>>();

    resid_ln_expand_kernel<<<dim3(MROWS, 3), 256>>>(ax, sg, co, lnS0, lnB0, lnS1, lnB1, lnS2, lnB2);

    hgemm<0><<<dim3(2, 64, 2), 256>>>(Ahp, Whp, (const float*)0, Kpp, (void*)0, (void*)0,
                                      MROWS, DIM, KEXP, KEXP / 2);
    kan_reduce<<<MROWS * DIM / 4 / 256, 256>>>(out);
}

// round 15
// speedup vs baseline: 1.0696x; 1.0487x over previous
#include <cuda_runtime.h>
#include <cuda_fp16.h>
#include <math.h>
#include <cstdint>

#define S_LEN 4096
#define DIM   256
#define MROWS 8192
#define IN_F  768
#define KEXP  6912
#define PIECE (3ull * MROWS * DIM)
#define NROWS (3 * MROWS)
#define QSCALE 0.09016844f   // log2(e)/16

__device__ __half g_Ah[(size_t)MROWS * KEXP];
__device__ __half g_Wh[(size_t)DIM * KEXP];
__device__ __half g_T16[3ull * MROWS * DIM];
__device__ __half g_Wqkv[768ull * DIM];
__device__ float  g_bqkv[768];
__device__ __half g_Qb[3ull * MROWS * DIM];
__device__ __half g_Kb[3ull * MROWS * DIM];
__device__ __half g_Vb[3ull * MROWS * DIM];
__device__ float g_Ap[3ull * PIECE];
__device__ float g_L[3 * NROWS];
__device__ float g_Kp[2ull * MROWS * DIM];

// ======================= PTX helpers (baseline sm_103) =====================
__device__ __forceinline__ uint32_t smem_u32(const void* p) {
    uint32_t a;
    asm("{ .reg .u64 t; cvta.to.shared.u64 t, %1; cvt.u32.u64 %0, t; }" : "=r"(a) : "l"(p));
    return a;
}
#define LDSM4(d0, d1, d2, d3, a)                                                        \
    asm volatile("ldmatrix.sync.aligned.m8n8.x4.shared.b16 {%0,%1,%2,%3}, [%4];"        \
                 : "=r"(d0), "=r"(d1), "=r"(d2), "=r"(d3) : "r"(a))
#define LDSM4T(d0, d1, d2, d3, a)                                                       \
    asm volatile("ldmatrix.sync.aligned.m8n8.x4.trans.shared.b16 {%0,%1,%2,%3}, [%4];"  \
                 : "=r"(d0), "=r"(d1), "=r"(d2), "=r"(d3) : "r"(a))
#define MMAH(c, a0, a1, a2, a3, b0, b1)                                                 \
    asm volatile("mma.sync.aligned.m16n8k16.row.col.f32.f16.f16.f32 "                   \
                 "{%0,%1,%2,%3}, {%4,%5,%6,%7}, {%8,%9}, {%0,%1,%2,%3};"                \
                 : "+f"((c)[0]), "+f"((c)[1]), "+f"((c)[2]), "+f"((c)[3])               \
                 : "r"(a0), "r"(a1), "r"(a2), "r"(a3), "r"(b0), "r"(b1))
#define CPA16(d, s) asm volatile("cp.async.cg.shared.global [%0], [%1], 16;" :: "r"(d), "l"(s))
#define CPCOMMIT()  asm volatile("cp.async.commit_group;" ::: "memory")
#define CPWAIT1()   asm volatile("cp.async.wait_group 1;" ::: "memory")
#define CPWAIT0()   asm volatile("cp.async.wait_group 0;" ::: "memory")
#define EX2H2(d, s) asm("ex2.approx.f16x2 %0, %1;" : "=r"(d) : "r"(s))

// ================== HMMA GEMM: C[M,N] = A[M,K] @ W[N,K]^T ==================
// BM=128, BN=128, BK=32, 256 thr, 3-stage cp.async, ONE sync per k-iter.
// MODE 0: KAN split-K (z = K-piece, fp32 partial out).
// MODE 1: QKV (z = view; fp16 out split q/k/v by col>>8; Q pre-scaled).
template <int MODE>
__global__ void __launch_bounds__(256) hgemm(const __half* __restrict__ A,
                                             const __half* __restrict__ W,
                                             const float* __restrict__ bias,
                                             void* __restrict__ C0,
                                             void* __restrict__ C1,
                                             void* __restrict__ C2,
                                             int M, int N, int Kst, int Klen) {
    __shared__ __align__(16) char sA[3][8192];
    __shared__ __align__(16) char sW[3][8192];
    uint32_t aB = smem_u32(sA), wB = smem_u32(sW);
    int tid = threadIdx.x, lane = tid & 31, w = tid >> 5;
    int wm = w >> 2, wn = w & 3;
    int m0 = blockIdx.y << 7, n0 = blockIdx.x << 7;
    int z = blockIdx.z;
    int lrow = lane & 7, lhalf = (lane >> 3) & 1, lhi = lane >> 4;

    const __half* Ab = (MODE == 0) ? A + (size_t)z * Klen : A + (size_t)z * MROWS * DIM;
    const __half* Wb = (MODE == 0) ? W + (size_t)z * Klen : W;

    int r0 = tid >> 2, c0 = tid & 3;
    int r1 = (tid + 256) >> 2, c1 = (tid + 256) & 3;
    uint32_t dA0 = r0 * 64 + ((c0 ^ ((r0 >> 1) & 3)) << 4);
    uint32_t dA1 = r1 * 64 + ((c1 ^ ((r1 >> 1) & 3)) << 4);
    const __half* As0 = Ab + (size_t)(m0 + r0) * Kst + c0 * 8;
    const __half* As1 = Ab + (size_t)(m0 + r1) * Kst + c1 * 8;
    const __half* Ws0 = Wb + (size_t)(n0 + r0) * Kst + c0 * 8;
    const __half* Ws1 = Wb + (size_t)(n0 + r1) * Kst + c1 * 8;

    int rowA[4], xrA[4];
#pragma unroll
    for (int mi = 0; mi < 4; mi++) {
        rowA[mi] = wm * 64 + mi * 16 + lrow + (lhalf << 3);
        xrA[mi] = (rowA[mi] >> 1) & 3;
    }
    int rowW[2], xrW[2];
#pragma unroll
    for (int ng = 0; ng < 2; ng++) {
        rowW[ng] = wn * 32 + ng * 16 + lrow + (lhalf << 3);
        xrW[ng] = (rowW[ng] >> 1) & 3;
    }

    float oacc[4][4][4];
#pragma unroll
    for (int i = 0; i < 4; i++)
#pragma unroll
        for (int j = 0; j < 4; j++)
#pragma unroll
            for (int e = 0; e < 4; e++) oacc[i][j][e] = 0.0f;

    int KT = Klen >> 5;
    auto issue = [&](int kt) {
        uint32_t so = (uint32_t)(kt % 3) * 8192;
        int nk = kt << 5;
        CPA16(aB + so + dA0, As0 + nk); CPA16(aB + so + dA1, As1 + nk);
        CPA16(wB + so + dA0, Ws0 + nk); CPA16(wB + so + dA1, Ws1 + nk);
        CPCOMMIT();
    };
    issue(0);
    issue(1);

    for (int kt = 0; kt < KT; kt++) {
        if (kt + 1 < KT) { CPWAIT1(); } else { CPWAIT0(); }
        __syncthreads();
        if (kt + 2 < KT) issue(kt + 2);   // safe after sync: prior readers done
        uint32_t so = (uint32_t)(kt % 3) * 8192;
        uint32_t aS = aB + so, wS = wB + so;
#pragma unroll
        for (int kk = 0; kk < 2; kk++) {
            uint32_t a[4][4];
#pragma unroll
            for (int mi = 0; mi < 4; mi++)
                LDSM4(a[mi][0], a[mi][1], a[mi][2], a[mi][3],
                      aS + rowA[mi] * 64 + (((2 * kk + lhi) ^ xrA[mi]) << 4));
#pragma unroll
            for (int ng = 0; ng < 2; ng++) {
                uint32_t b0, b1, b2, b3;
                LDSM4(b0, b1, b2, b3,
                      wS + rowW[ng] * 64 + (((2 * kk + lhi) ^ xrW[ng]) << 4));
#pragma unroll
                for (int mi = 0; mi < 4; mi++) {
                    MMAH(oacc[mi][2 * ng], a[mi][0], a[mi][1], a[mi][2], a[mi][3], b0, b2);
                    MMAH(oacc[mi][2 * ng + 1], a[mi][0], a[mi][1], a[mi][2], a[mi][3], b1, b3);
                }
            }
        }
    }

    int gid = lane >> 2, tig = lane & 3;
    float qs = (MODE == 1 && (n0 >> 8) == 0) ? QSCALE : 1.0f;
#pragma unroll
    for (int mi = 0; mi < 4; mi++) {
        int row0 = m0 + wm * 64 + mi * 16 + gid;
#pragma unroll
        for (int nj = 0; nj < 4; nj++) {
            int colw = wn * 32 + nj * 8 + tig * 2;
            float b0 = 0.f, b1 = 0.f;
            if (MODE == 1) { b0 = bias[n0 + colw]; b1 = bias[n0 + colw + 1]; }
            float v00 = (oacc[mi][nj][0] + b0) * qs, v01 = (oacc[mi][nj][1] + b1) * qs;
            float v10 = (oacc[mi][nj][2] + b0) * qs, v11 = (oacc[mi][nj][3] + b1) * qs;
            if (MODE == 0) {
                float* Cp = (float*)C0 + (size_t)z * MROWS * DIM;
                *(float2*)(Cp + (size_t)row0 * N + n0 + colw) = make_float2(v00, v01);
                *(float2*)(Cp + (size_t)(row0 + 8) * N + n0 + colw) = make_float2(v10, v11);
            } else {
                int sel = n0 >> 8;
                __half* dst = (__half*)(sel == 0 ? C0 : (sel == 1 ? C1 : C2)) + (size_t)z * MROWS * DIM;
                int col = (n0 & 255) + colw;
                *(__half2*)(dst + (size_t)row0 * DIM + col) = __floats2half2_rn(v00, v01);
                *(__half2*)(dst + (size_t)(row0 + 8) * DIM + col) = __floats2half2_rn(v10, v11);
            }
        }
    }
}

// ================== split-K reduce -> d_out ================================
__global__ void __launch_bounds__(256) kan_reduce(float* __restrict__ out) {
    size_t i = ((size_t)blockIdx.x * 256 + threadIdx.x) * 4;
    float4 a = *(float4*)(g_Kp + i);
    float4 b = *(float4*)(g_Kp + (size_t)MROWS * DIM + i);
    *(float4*)(out + i) = make_float4(a.x + b.x, a.y + b.y, a.z + b.z, a.w + b.w);
}

// ================== packers ================================================
__global__ void __launch_bounds__(256) tok2half(const float* __restrict__ t0,
                                                const float* __restrict__ t1,
                                                const float* __restrict__ t2) {
    size_t i = (size_t)blockIdx.x * 256 + threadIdx.x;
    size_t n = (size_t)MROWS * DIM / 4;
    const float4* src = i < n ? (const float4*)t0 : (i < 2 * n ? (const float4*)t1 : (const float4*)t2);
    float4 v = src[i % n];
    *(__half2*)(g_T16 + i * 4) = __floats2half2_rn(v.x, v.y);
    *(__half2*)(g_T16 + i * 4 + 2) = __floats2half2_rn(v.z, v.w);
}

__global__ void __launch_bounds__(256) pack_wqkv(const float* __restrict__ wq, const float* __restrict__ bq,
                                                 const float* __restrict__ wk, const float* __restrict__ bk,
                                                 const float* __restrict__ wv, const float* __restrict__ bv) {
    int o = blockIdx.x;
    int k = threadIdx.x;
    int sel = o >> 8, oo = o & 255;
    const float* wsrc = sel == 0 ? wq : (sel == 1 ? wk : wv);
    g_Wqkv[(size_t)o * DIM + k] = __float2half(wsrc[(size_t)oo * DIM + k]);
    if (k == 0) {
        const float* bsrc = sel == 0 ? bq : (sel == 1 ? bk : bv);
        g_bqkv[o] = bsrc[oo];
    }
}

__global__ void __launch_bounds__(256) wcombine_kernel(const float* __restrict__ bw,
                                                       const float* __restrict__ sw,
                                                       const float* __restrict__ ss) {
    int k = blockIdx.x * 256 + threadIdx.x;
    int o = blockIdx.y;
    float w;
    if (k < IN_F) {
        w = bw[(size_t)o * IN_F + k];
    } else {
        int kk = k - IN_F;
        int i = kk >> 3, f = kk & 7;
        w = sw[((size_t)o * IN_F + i) * 8 + f] * ss[(size_t)o * IN_F + i];
    }
    g_Wh[(size_t)o * KEXP + k] = __float2half(w);
}

// ============ HMMA flash attention, split-KV(3), cp.async x2 ===============
// Q pre-scaled by log2(e)/16 -> P = ex2(S) directly; ONE sync per KV-iter
// (issue moved after the barrier, so the trailing barrier is unnecessary).
#define FMM_SMEM 196608
#define SKO 65536
#define SVO 131072

__global__ void __launch_bounds__(256, 1) flash_mma_kernel() {
    extern __shared__ char sm[];
    uint32_t sb = smem_u32(sm);
    int tid = threadIdx.x, lane = tid & 31, w = tid >> 5;
    int lrow = lane & 7, lhalf = (lane >> 3) & 1, lhi = lane >> 4;
    int vw = blockIdx.y >> 1, bt = blockIdx.y & 1, q0 = blockIdx.x << 7;
    int z = blockIdx.z;
    int k0 = z == 0 ? 0 : (z == 1 ? 22 : 43);
    int k1 = z == 0 ? 22 : (z == 1 ? 43 : 64);
    int nkt = k1 - k0;
    size_t rowidx = (size_t)vw * MROWS + (size_t)bt * S_LEN;

    {
        const uint4* Qg = (const uint4*)(g_Qb + (rowidx + q0) * DIM);
#pragma unroll
        for (int it = 0; it < 16; it++) {
            int idx = tid + it * 256;
            int r = idx >> 5, c = idx & 31;
            *(uint4*)(sm + r * 512 + ((c ^ (r & 7)) << 4)) = Qg[idx];
        }
    }

    uint32_t dsto[8];
#pragma unroll
    for (int it = 0; it < 8; it++) {
        int idx = tid + it * 256;
        int r = idx >> 5, c = idx & 31;
        dsto[it] = r * 512 + ((c ^ (r & 7)) << 4);
    }
    auto issue = [&](int kt, int buf) {
        const char* Kg = (const char*)(g_Kb + (rowidx + (size_t)kt * 64) * DIM);
        const char* Vg = (const char*)(g_Vb + (rowidx + (size_t)kt * 64) * DIM);
        uint32_t kb = sb + SKO + buf * 32768, vb = sb + SVO + buf * 32768;
#pragma unroll
        for (int it = 0; it < 8; it++) {
            size_t so = (size_t)(tid + it * 256) * 16;
            CPA16(kb + dsto[it], Kg + so);
            CPA16(vb + dsto[it], Vg + so);
        }
        CPCOMMIT();
    };

    uint32_t qbase = sb + ((w << 4) + lrow + (lhalf << 3)) * 512;
    uint32_t rroff[4];
#pragma unroll
    for (int t = 0; t < 4; t++)
        rroff[t] = (t * 16 + lrow + (lhalf << 3)) * 512;

    float oacc[32][4];
#pragma unroll
    for (int i = 0; i < 32; i++)
#pragma unroll
        for (int j = 0; j < 4; j++) oacc[i][j] = 0.0f;
    float lsum0 = 0.0f, lsum1 = 0.0f;

    issue(k0, 0);

    for (int i = 0; i < nkt; i++) {
        int cur = i & 1;
        CPWAIT0();
        __syncthreads();   // buffer cur visible to all; prior readers done
        if (i + 1 < nkt) issue(k0 + i + 1, 1 - cur);

        uint32_t kS = sb + SKO + cur * 32768, vS = sb + SVO + cur * 32768;

        // ---- S = Q @ K^T (pre-scaled into log2 domain) ----
        float sacc[8][4];
#pragma unroll
        for (int ii = 0; ii < 8; ii++)
#pragma unroll
            for (int j = 0; j < 4; j++) sacc[ii][j] = 0.0f;
#pragma unroll
        for (int ks = 0; ks < 16; ks++) {
            uint32_t chq = (uint32_t)(((2 * ks + lhi) ^ lrow) << 4);
            uint32_t a0, a1, a2, a3;
            LDSM4(a0, a1, a2, a3, qbase + chq);
#pragma unroll
            for (int kb = 0; kb < 4; kb++) {
                uint32_t b0, b1, b2, b3;
                LDSM4(b0, b1, b2, b3, kS + rroff[kb] + chq);
                MMAH(sacc[2 * kb], a0, a1, a2, a3, b0, b2);
                MMAH(sacc[2 * kb + 1], a0, a1, a2, a3, b1, b3);
            }
        }

        // ---- per-kc: P = ex2(S) in fp16x2, then O += P @ V ----
        __half2 hs0 = __floats2half2_rn(0.f, 0.f);
        __half2 hs1 = hs0;
#pragma unroll
        for (int kc = 0; kc < 4; kc++) {
            uint32_t pa[4];
#pragma unroll
            for (int jj = 0; jj < 2; jj++) {
                int j = 2 * kc + jj;
                __half2 t01 = __floats2half2_rn(sacc[j][0], sacc[j][1]);
                __half2 t23 = __floats2half2_rn(sacc[j][2], sacc[j][3]);
                uint32_t p01, p23;
                EX2H2(p01, *(uint32_t*)&t01);
                EX2H2(p23, *(uint32_t*)&t23);
                pa[2 * jj] = p01;
                pa[2 * jj + 1] = p23;
                hs0 = __hadd2(hs0, *(__half2*)&p01);
                hs1 = __hadd2(hs1, *(__half2*)&p23);
            }
#pragma unroll
            for (int nn = 0; nn < 16; nn++) {
                uint32_t r0, r1, r2, r3;
                LDSM4T(r0, r1, r2, r3, vS + rroff[kc] + (((2 * nn + lhi) ^ lrow) << 4));
                MMAH(oacc[2 * nn], pa[0], pa[1], pa[2], pa[3], r0, r1);
                MMAH(oacc[2 * nn + 1], pa[0], pa[1], pa[2], pa[3], r2, r3);
            }
        }
        float2 f0 = __half22float2(hs0);
        float2 f1 = __half22float2(hs1);
        lsum0 += f0.x + f0.y;
        lsum1 += f1.x + f1.y;
    }

    lsum0 += __shfl_xor_sync(0xffffffffu, lsum0, 1);
    lsum0 += __shfl_xor_sync(0xffffffffu, lsum0, 2);
    lsum1 += __shfl_xor_sync(0xffffffffu, lsum1, 1);
    lsum1 += __shfl_xor_sync(0xffffffffu, lsum1, 2);
    int gid = lane >> 2, tig = lane & 3;
    int row0 = q0 + (w << 4) + gid;
    if (tig == 0) {
        g_L[z * NROWS + rowidx + row0] = lsum0;
        g_L[z * NROWS + rowidx + row0 + 8] = lsum1;
    }
    float* o0 = g_Ap + (size_t)z * PIECE + (rowidx + row0) * DIM;
    float* o1 = o0 + 8 * DIM;
#pragma unroll
    for (int nt = 0; nt < 32; nt++) {
        int col = nt * 8 + tig * 2;
        *(float2*)(o0 + col) = make_float2(oacc[nt][0], oacc[nt][1]);
        *(float2*)(o1 + col) = make_float2(oacc[nt][2], oacc[nt][3]);
    }
}

// ====== fused: merge KV pieces + residual + LN + silu/spline expand ========
__global__ void __launch_bounds__(256) resid_ln_expand_kernel(
    const float* __restrict__ t0, const float* __restrict__ t1, const float* __restrict__ t2,
    const float* __restrict__ s0, const float* __restrict__ b0,
    const float* __restrict__ s1, const float* __restrict__ b1,
    const float* __restrict__ s2, const float* __restrict__ b2) {
    __shared__ float ps[16];
    int r = blockIdx.x, v = blockIdx.y, c = threadIdx.x;
    int lane = c & 31, wid = c >> 5;
    const float* tok = v == 0 ? t0 : (v == 1 ? t1 : t2);
    const float* sc = v == 0 ? s0 : (v == 1 ? s1 : s2);
    const float* bi = v == 0 ? b0 : (v == 1 ? b1 : b2);
    size_t row = (size_t)v * MROWS + r;
    float l = g_L[row] + g_L[NROWS + row] + g_L[2 * NROWS + row];
    size_t e = row * DIM + c;
    float o = g_Ap[e] + g_Ap[PIECE + e] + g_Ap[2 * PIECE + e];
    float a = o / l + tok[(size_t)r * DIM + c];
    float s1v = a, s2v = a * a;
#pragma unroll
    for (int off = 16; off > 0; off >>= 1) {
        s1v += __shfl_xor_sync(0xffffffffu, s1v, off);
        s2v += __shfl_xor_sync(0xffffffffu, s2v, off);
    }
    if (lane == 0) { ps[wid] = s1v; ps[8 + wid] = s2v; }
    __syncthreads();
    float t1s = 0.f, t2s = 0.f;
#pragma unroll
    for (int q = 0; q < 8; q++) { t1s += ps[q]; t2s += ps[8 + q]; }
    float mu = t1s * (1.0f / 256.0f);
    float var = t2s * (1.0f / 256.0f) - mu * mu;
    float x = (a - mu) * rsqrtf(var + 1e-5f) * sc[c] + bi[c];

    int i = v * DIM + c;
    __half* Ar = g_Ah + (size_t)r * KEXP;
    Ar[i] = __float2half(x / (1.0f + expf(-x)));
    float g[12];
#pragma unroll
    for (int j = 0; j < 12; j++) g[j] = (float)(j - 3) * 0.4f + (-1.0f);
    float b[11];
#pragma unroll
    for (int t = 0; t < 11; t++) b[t] = (x >= g[t] && x < g[t + 1]) ? 1.0f : 0.0f;
#pragma unroll
    for (int k = 1; k <= 3; k++) {
#pragma unroll
        for (int t = 0; t + k < 11; t++)
            b[t] = (x - g[t]) / (g[t + k] - g[t]) * b[t]
                 + (g[t + k + 1] - x) / (g[t + k + 1] - g[t + 1]) * b[t + 1];
    }
    __half2 h0 = __floats2half2_rn(b[0], b[1]);
    __half2 h1 = __floats2half2_rn(b[2], b[3]);
    __half2 h2 = __floats2half2_rn(b[4], b[5]);
    __half2 h3 = __floats2half2_rn(b[6], b[7]);
    uint4 pk = make_uint4(*(uint32_t*)&h0, *(uint32_t*)&h1, *(uint32_t*)&h2, *(uint32_t*)&h3);
    *(uint4*)(Ar + IN_F + (size_t)i * 8) = pk;
}

extern "C" void kernel_launch(void* const* d_in, const int* in_sizes, int n_in,
                              void* d_out, int out_size) {
    const float* ax = (const float*)d_in[0];
    const float* sg = (const float*)d_in[1];
    const float* co = (const float*)d_in[2];
    const float* wq = (const float*)d_in[3];
    const float* bq = (const float*)d_in[4];
    const float* wk = (const float*)d_in[5];
    const float* bk = (const float*)d_in[6];
    const float* wv = (const float*)d_in[7];
    const float* bv = (const float*)d_in[8];
    // d_in[9] = view_emb: softmax-invariant, unused.
    const float* lnS0 = (const float*)d_in[10];
    const float* lnB0 = (const float*)d_in[11];
    const float* lnS1 = (const float*)d_in[12];
    const float* lnB1 = (const float*)d_in[13];
    const float* lnS2 = (const float*)d_in[14];
    const float* lnB2 = (const float*)d_in[15];
    const float* bw = (const float*)d_in[16];
    const float* sw = (const float*)d_in[17];
    const float* ss = (const float*)d_in[18];
    float* out = (float*)d_out;

    __half *Qp, *Kp, *Vp, *Tp, *Wqkvp, *Ahp, *Whp;
    float *bqkvp, *Kpp;
    cudaGetSymbolAddress((void**)&Qp, g_Qb);
    cudaGetSymbolAddress((void**)&Kp, g_Kb);
    cudaGetSymbolAddress((void**)&Vp, g_Vb);
    cudaGetSymbolAddress((void**)&Tp, g_T16);
    cudaGetSymbolAddress((void**)&Wqkvp, g_Wqkv);
    cudaGetSymbolAddress((void**)&bqkvp, g_bqkv);
    cudaGetSymbolAddress((void**)&Ahp, g_Ah);
    cudaGetSymbolAddress((void**)&Whp, g_Wh);
    cudaGetSymbolAddress((void**)&Kpp, g_Kp);
    cudaFuncSetAttribute(flash_mma_kernel, cudaFuncAttributeMaxDynamicSharedMemorySize, FMM_SMEM);

    tok2half<<<3 * MROWS * DIM / 4 / 256, 256>>>(ax, sg, co);
    pack_wqkv<<<768, 256>>>(wq, bq, wk, bk, wv, bv);
    wcombine_kernel<<<dim3(KEXP / 256, DIM), 256>>>(bw, sw, ss);

    hgemm<1><<<dim3(6, 64, 3), 256>>>(Tp, Wqkvp, bqkvp, Qp, Kp, Vp, MROWS, 768, DIM, DIM);

    flash_mma_kernel<<<dim3(32, 6, 3), 256, FMM_SMEM>>>();

    resid_ln_expand_kernel<<<dim3(MROWS, 3), 256>>>(ax, sg, co, lnS0, lnB0, lnS1, lnB1, lnS2, lnB2);

    hgemm<0><<<dim3(2, 64, 2), 256>>>(Ahp, Whp, (const float*)0, Kpp, (void*)0, (void*)0,
                                      MROWS, DIM, KEXP, KEXP / 2);
    kan_reduce<<<MROWS * DIM / 4 / 256, 256>>>(out);
}